// round 9
// baseline (speedup 1.0000x reference)
#include <cuda_runtime.h>
#include <cuda_bf16.h>

#define NA 8192
#define NP 65536
#define FDIM 128
#define RD 20
#define NB 5
#define TMX 8

// Scratch (allocation-free rule: __device__ globals)
__device__ __align__(16) float g_x[NA * 384];
__device__ __align__(16) float g_dq[NA * FDIM];
__device__ __align__(16) float g_dmu[NA * 384];
__device__ int g_cnt[NA];
__device__ int g_offs[NA + 1];
__device__ int g_cursor[NA];
__device__ int g_csr[NP];

__device__ __forceinline__ float silu(float z) { return z / (1.f + __expf(-z)); }

// ---------------------------------------------------------------------------
// CSR build: histogram -> single-CTA scan -> scatter. idx_i static per launch.
// ---------------------------------------------------------------------------
__global__ void __launch_bounds__(256) k_hist(const int* __restrict__ idx_i)
{
    int p = blockIdx.x * 256 + threadIdx.x;
    if (p < NP) atomicAdd(&g_cnt[idx_i[p]], 1);
}

__global__ void __launch_bounds__(1024) k_scan()
{
    __shared__ int s[1024];
    const int tid = threadIdx.x;
    const int base = tid * 8;
    int v[8];
    int sum = 0;
#pragma unroll
    for (int t = 0; t < 8; t++) { v[t] = g_cnt[base + t]; sum += v[t]; }
    s[tid] = sum;
    __syncthreads();
    for (int off = 1; off < 1024; off <<= 1) {
        int x = (tid >= off) ? s[tid - off] : 0;
        __syncthreads();
        s[tid] += x;
        __syncthreads();
    }
    int run = s[tid] - sum;   // exclusive prefix of this thread's chunk
#pragma unroll
    for (int t = 0; t < 8; t++) {
        g_offs[base + t] = run;
        g_cursor[base + t] = run;
        run += v[t];
    }
    if (tid == 1023) g_offs[NA] = run;
}

__global__ void __launch_bounds__(256) k_scatter(const int* __restrict__ idx_i)
{
    int p = blockIdx.x * 256 + threadIdx.x;
    if (p < NP) {
        int pos = atomicAdd(&g_cursor[idx_i[p]], 1);
        g_csr[pos] = p;
    }
}

// ---------------------------------------------------------------------------
// k_x: x = silu(q @ W1 + b1) @ W2 + b2.  8 atoms/CTA, 128 threads, 1 col/thr.
// ---------------------------------------------------------------------------
__global__ void __launch_bounds__(128) k_x(
    const float* __restrict__ q,
    const float* __restrict__ W1, const float* __restrict__ b1,
    const float* __restrict__ W2, const float* __restrict__ b2,
    float* __restrict__ x)
{
    __shared__ __align__(16) float qs[TMX * FDIM];
    __shared__ __align__(16) float hs[TMX * FDIM];
    const int tid = threadIdx.x;
    const int atom0 = blockIdx.x * TMX;
    const int f = tid;

    {
        const float4* src = (const float4*)(q + atom0 * FDIM);
        float4* dst = (float4*)qs;
        for (int c = tid; c < TMX * 32; c += 128) dst[c] = src[c];
    }
    __syncthreads();

    const float4* qs4 = (const float4*)qs;
    {
        float acc[TMX];
#pragma unroll
        for (int a = 0; a < TMX; a++) acc[a] = 0.f;
#pragma unroll 2
        for (int kp = 0; kp < 32; kp++) {
            const float w0 = W1[(4 * kp)     * FDIM + f];
            const float w1 = W1[(4 * kp + 1) * FDIM + f];
            const float w2 = W1[(4 * kp + 2) * FDIM + f];
            const float w3 = W1[(4 * kp + 3) * FDIM + f];
#pragma unroll
            for (int a = 0; a < TMX; a++) {
                const float4 v = qs4[a * 32 + kp];
                acc[a] += v.x * w0 + v.y * w1 + v.z * w2 + v.w * w3;
            }
        }
        const float bb = b1[f];
#pragma unroll
        for (int a = 0; a < TMX; a++) hs[a * FDIM + f] = silu(acc[a] + bb);
    }
    __syncthreads();

    {
        const float4* hs4 = (const float4*)hs;
        float accA[TMX], accB[TMX], accC[TMX];
#pragma unroll
        for (int a = 0; a < TMX; a++) { accA[a] = 0.f; accB[a] = 0.f; accC[a] = 0.f; }
#pragma unroll 2
        for (int kp = 0; kp < 32; kp++) {
            float wa[4], wb[4], wc[4];
#pragma unroll
            for (int t = 0; t < 4; t++) {
                wa[t] = W2[(4 * kp + t) * 384 + f];
                wb[t] = W2[(4 * kp + t) * 384 + FDIM + f];
                wc[t] = W2[(4 * kp + t) * 384 + 2 * FDIM + f];
            }
#pragma unroll
            for (int a = 0; a < TMX; a++) {
                const float4 v = hs4[a * 32 + kp];
                accA[a] += v.x * wa[0] + v.y * wa[1] + v.z * wa[2] + v.w * wa[3];
                accB[a] += v.x * wb[0] + v.y * wb[1] + v.z * wb[2] + v.w * wb[3];
                accC[a] += v.x * wc[0] + v.y * wc[1] + v.z * wc[2] + v.w * wc[3];
            }
        }
        const float bA = b2[f], bB = b2[FDIM + f], bC = b2[2 * FDIM + f];
#pragma unroll
        for (int a = 0; a < TMX; a++) {
            x[(atom0 + a) * 384 + f]            = accA[a] + bA;
            x[(atom0 + a) * 384 + FDIM + f]     = accB[a] + bB;
            x[(atom0 + a) * 384 + 2 * FDIM + f] = accC[a] + bC;
        }
    }
}

// ---------------------------------------------------------------------------
// k_pairs_g: CSR gather. One warp per atom i, lane = 4 features. Loops the
// atom's pair list, computes the filter + messages, accumulates in REGISTERS,
// single plain store at the end. No atomics, no memsets.
// ---------------------------------------------------------------------------
__global__ void __launch_bounds__(128) k_pairs_g(
    const float* __restrict__ x, const float* __restrict__ mu,
    const float* __restrict__ dist, const float* __restrict__ vec,
    const float* __restrict__ cut, const float* __restrict__ rbf,
    const float* __restrict__ fW,   // pre-offset by b*384, row stride 1920
    const float* __restrict__ fb,   // pre-offset by b*384
    const int* __restrict__ idx_j,
    float* __restrict__ dq, float* __restrict__ dmu)
{
    __shared__ __align__(16) float fw_s[RD * 384];
    __shared__ __align__(16) float fb_s[384];
    const int tid = threadIdx.x;
    for (int c = tid; c < RD * 384; c += 128) {
        int r = c / 384, cc = c - r * 384;
        fw_s[c] = fW[r * 1920 + cc];
    }
    for (int c = tid; c < 384; c += 128) fb_s[c] = fb[c];
    __syncthreads();

    const int lane = tid & 31;
    const int atom = blockIdx.x * 4 + (tid >> 5);
    const int s0 = g_offs[atom];
    const int s1 = g_offs[atom + 1];

    const float4* fw4 = (const float4*)fw_s;   // [RD][96]
    const float4* fb4 = (const float4*)fb_s;   // [96]
    const float4* X4 = (const float4*)x;       // [NA][96]
    const float4* M4 = (const float4*)mu;      // [NA*3][32]

    float4 aq = make_float4(0.f, 0.f, 0.f, 0.f);
    float4 am0 = aq, am1 = aq, am2 = aq;

    for (int k = s0; k < s1; k++) {
        const int p = g_csr[k];
        const int j = idx_j[p];
        const float dinv = 1.f / dist[p];
        const float cu = cut[p];
        const float d0 = vec[3 * p] * dinv;
        const float d1 = vec[3 * p + 1] * dinv;
        const float d2 = vec[3 * p + 2] * dinv;

        float4 wq = make_float4(0.f, 0.f, 0.f, 0.f);
        float4 wr = wq, wm = wq;
#pragma unroll
        for (int r = 0; r < RD; r++) {
            float rb = rbf[p * RD + r];
            float4 t;
            t = fw4[r * 96 + lane];
            wq.x += rb * t.x; wq.y += rb * t.y; wq.z += rb * t.z; wq.w += rb * t.w;
            t = fw4[r * 96 + 32 + lane];
            wr.x += rb * t.x; wr.y += rb * t.y; wr.z += rb * t.z; wr.w += rb * t.w;
            t = fw4[r * 96 + 64 + lane];
            wm.x += rb * t.x; wm.y += rb * t.y; wm.z += rb * t.z; wm.w += rb * t.w;
        }
        {
            float4 t = fb4[lane];
            wq.x = (wq.x + t.x) * cu; wq.y = (wq.y + t.y) * cu;
            wq.z = (wq.z + t.z) * cu; wq.w = (wq.w + t.w) * cu;
            t = fb4[32 + lane];
            wr.x = (wr.x + t.x) * cu; wr.y = (wr.y + t.y) * cu;
            wr.z = (wr.z + t.z) * cu; wr.w = (wr.w + t.w) * cu;
            t = fb4[64 + lane];
            wm.x = (wm.x + t.x) * cu; wm.y = (wm.y + t.y) * cu;
            wm.z = (wm.z + t.z) * cu; wm.w = (wm.w + t.w) * cu;
        }
        const float4 xq = X4[j * 96 + lane];
        const float4 xr = X4[j * 96 + 32 + lane];
        const float4 xm = X4[j * 96 + 64 + lane];

        aq.x += xq.x * wq.x; aq.y += xq.y * wq.y;
        aq.z += xq.z * wq.z; aq.w += xq.w * wq.w;

        const float ax = xr.x * wr.x, ay = xr.y * wr.y, az = xr.z * wr.z, aw = xr.w * wr.w;
        const float cx = xm.x * wm.x, cy = xm.y * wm.y, cz = xm.z * wm.z, cw = xm.w * wm.w;

        const float4 mj0 = M4[(j * 3 + 0) * 32 + lane];
        am0.x += ax * d0 + cx * mj0.x; am0.y += ay * d0 + cy * mj0.y;
        am0.z += az * d0 + cz * mj0.z; am0.w += aw * d0 + cw * mj0.w;
        const float4 mj1 = M4[(j * 3 + 1) * 32 + lane];
        am1.x += ax * d1 + cx * mj1.x; am1.y += ay * d1 + cy * mj1.y;
        am1.z += az * d1 + cz * mj1.z; am1.w += aw * d1 + cw * mj1.w;
        const float4 mj2 = M4[(j * 3 + 2) * 32 + lane];
        am2.x += ax * d2 + cx * mj2.x; am2.y += ay * d2 + cy * mj2.y;
        am2.z += az * d2 + cz * mj2.z; am2.w += aw * d2 + cw * mj2.w;
    }

    ((float4*)dq)[atom * 32 + lane] = aq;
    ((float4*)dmu)[(atom * 3 + 0) * 32 + lane] = am0;
    ((float4*)dmu)[(atom * 3 + 1) * 32 + lane] = am1;
    ((float4*)dmu)[(atom * 3 + 2) * 32 + lane] = am2;
}

// ---------------------------------------------------------------------------
// k_mix: fold deltas; mu@Wv with running norm^2 and V.W dot in registers;
// mixing MLP; gated update. 8 atoms/CTA, 128 threads, 1 col/thr.
// ---------------------------------------------------------------------------
__global__ void __launch_bounds__(128) k_mix(
    float* __restrict__ q, float* __restrict__ mu,
    const float* __restrict__ dq, const float* __restrict__ dmu,
    const float* __restrict__ Wv,                                  // [128][256]
    const float* __restrict__ mW1, const float* __restrict__ mb1,  // [256][128]
    const float* __restrict__ mW2, const float* __restrict__ mb2)  // [128][384]
{
    __shared__ __align__(16) float qs[8 * FDIM];
    __shared__ __align__(16) float mus[8 * 384];
    __shared__ __align__(16) float mws[8 * 384];
    __shared__ __align__(16) float ns[8 * FDIM];
    __shared__ __align__(16) float hs[8 * FDIM];

    const int tid = threadIdx.x;
    const int atom0 = blockIdx.x * 8;
    const int f = tid;

    {
        const float4* sq = (const float4*)(q + atom0 * FDIM);
        const float4* sdq = (const float4*)(dq + atom0 * FDIM);
        float4* dst = (float4*)qs;
        for (int c = tid; c < 8 * 32; c += 128) {
            float4 a = sq[c], b = sdq[c];
            dst[c] = make_float4(a.x + b.x, a.y + b.y, a.z + b.z, a.w + b.w);
        }
        const float4* sm = (const float4*)(mu + atom0 * 384);
        const float4* sdm = (const float4*)(dmu + atom0 * 384);
        float4* dstm = (float4*)mus;
        for (int c = tid; c < 8 * 96; c += 128) {
            float4 a = sm[c], b = sdm[c];
            dstm[c] = make_float4(a.x + b.x, a.y + b.y, a.z + b.z, a.w + b.w);
        }
    }
    __syncthreads();

    const float4* mus4 = (const float4*)mus;
    float nsq[8], dot[8];
#pragma unroll
    for (int a = 0; a < 8; a++) { nsq[a] = 0.f; dot[a] = 0.f; }

#pragma unroll 1
    for (int d = 0; d < 3; d++) {
        float accV[8], accW[8];
#pragma unroll
        for (int a = 0; a < 8; a++) { accV[a] = 0.f; accW[a] = 0.f; }
#pragma unroll 2
        for (int kp = 0; kp < 32; kp++) {
            float wv[4], ww[4];
#pragma unroll
            for (int t = 0; t < 4; t++) {
                wv[t] = Wv[(4 * kp + t) * 256 + f];
                ww[t] = Wv[(4 * kp + t) * 256 + FDIM + f];
            }
#pragma unroll
            for (int a = 0; a < 8; a++) {
                const float4 m = mus4[a * 96 + d * 32 + kp];
                accV[a] += m.x * wv[0] + m.y * wv[1] + m.z * wv[2] + m.w * wv[3];
                accW[a] += m.x * ww[0] + m.y * ww[1] + m.z * ww[2] + m.w * ww[3];
            }
        }
#pragma unroll
        for (int a = 0; a < 8; a++) {
            mws[a * 384 + d * FDIM + f] = accW[a];
            nsq[a] += accV[a] * accV[a];
            dot[a] += accV[a] * accW[a];
        }
    }
#pragma unroll
    for (int a = 0; a < 8; a++) ns[a * FDIM + f] = sqrtf(nsq[a] + 1e-8f);
    __syncthreads();

    {
        const float4* qs4 = (const float4*)qs;
        const float4* ns4 = (const float4*)ns;
        float acc[8];
#pragma unroll
        for (int a = 0; a < 8; a++) acc[a] = 0.f;
#pragma unroll 2
        for (int kp = 0; kp < 32; kp++) {
            float w[4];
#pragma unroll
            for (int t = 0; t < 4; t++) w[t] = mW1[(4 * kp + t) * FDIM + f];
#pragma unroll
            for (int a = 0; a < 8; a++) {
                const float4 v = qs4[a * 32 + kp];
                acc[a] += v.x * w[0] + v.y * w[1] + v.z * w[2] + v.w * w[3];
            }
        }
#pragma unroll 2
        for (int kp = 0; kp < 32; kp++) {
            float w[4];
#pragma unroll
            for (int t = 0; t < 4; t++) w[t] = mW1[(FDIM + 4 * kp + t) * FDIM + f];
#pragma unroll
            for (int a = 0; a < 8; a++) {
                const float4 v = ns4[a * 32 + kp];
                acc[a] += v.x * w[0] + v.y * w[1] + v.z * w[2] + v.w * w[3];
            }
        }
        const float bb = mb1[f];
#pragma unroll
        for (int a = 0; a < 8; a++) hs[a * FDIM + f] = silu(acc[a] + bb);
    }
    __syncthreads();

    {
        const float4* hs4 = (const float4*)hs;
        float accA[8], accB[8], accC[8];
#pragma unroll
        for (int a = 0; a < 8; a++) { accA[a] = 0.f; accB[a] = 0.f; accC[a] = 0.f; }
#pragma unroll 2
        for (int kp = 0; kp < 32; kp++) {
            float wa[4], wb[4], wc[4];
#pragma unroll
            for (int t = 0; t < 4; t++) {
                wa[t] = mW2[(4 * kp + t) * 384 + f];
                wb[t] = mW2[(4 * kp + t) * 384 + FDIM + f];
                wc[t] = mW2[(4 * kp + t) * 384 + 2 * FDIM + f];
            }
#pragma unroll
            for (int a = 0; a < 8; a++) {
                const float4 v = hs4[a * 32 + kp];
                accA[a] += v.x * wa[0] + v.y * wa[1] + v.z * wa[2] + v.w * wa[3];
                accB[a] += v.x * wb[0] + v.y * wb[1] + v.z * wb[2] + v.w * wb[3];
                accC[a] += v.x * wc[0] + v.y * wc[1] + v.z * wc[2] + v.w * wc[3];
            }
        }
        const float bA = mb2[f], bB = mb2[FDIM + f], bC = mb2[2 * FDIM + f];
#pragma unroll
        for (int a = 0; a < 8; a++) {
            const float yA = accA[a] + bA;
            const float yB = accB[a] + bB;
            const float yC = accC[a] + bC;
            q[(atom0 + a) * FDIM + f] = qs[a * FDIM + f] + yA + yC * dot[a];
#pragma unroll
            for (int d = 0; d < 3; d++)
                mu[(atom0 + a) * 384 + d * FDIM + f] =
                    mus[a * 384 + d * FDIM + f] + yB * mws[a * 384 + d * FDIM + f];
        }
    }
}

// ---------------------------------------------------------------------------
extern "C" void kernel_launch(void* const* d_in, const int* in_sizes, int n_in,
                              void* d_out, int out_size)
{
    const float* features = (const float*)d_in[0];
    const float* distances = (const float*)d_in[1];
    const float* vectors = (const float*)d_in[2];
    const float* cutoffs = (const float*)d_in[3];
    const float* rbfs = (const float*)d_in[4];
    const float* filter_W = (const float*)d_in[5];
    const float* filter_b = (const float*)d_in[6];
    const float* int_W1 = (const float*)d_in[7];
    const float* int_b1 = (const float*)d_in[8];
    const float* int_W2 = (const float*)d_in[9];
    const float* int_b2 = (const float*)d_in[10];
    const float* mix_Wv = (const float*)d_in[11];
    const float* mix_W1 = (const float*)d_in[12];
    const float* mix_b1 = (const float*)d_in[13];
    const float* mix_W2 = (const float*)d_in[14];
    const float* mix_b2 = (const float*)d_in[15];
    const int* idx_i = (const int*)d_in[16];
    const int* idx_j = (const int*)d_in[17];

    float* q = (float*)d_out;            // [NA,128]
    float* mu = q + NA * FDIM;           // [NA,3,128]

    float *xbuf, *dqbuf, *dmubuf;
    int* cntbuf;
    cudaGetSymbolAddress((void**)&xbuf, g_x);
    cudaGetSymbolAddress((void**)&dqbuf, g_dq);
    cudaGetSymbolAddress((void**)&dmubuf, g_dmu);
    cudaGetSymbolAddress((void**)&cntbuf, g_cnt);

    cudaMemcpyAsync(q, features, NA * FDIM * sizeof(float), cudaMemcpyDeviceToDevice);
    cudaMemsetAsync(mu, 0, NA * 384 * sizeof(float));

    // CSR build (idx_i static across blocks)
    cudaMemsetAsync(cntbuf, 0, NA * sizeof(int));
    k_hist<<<NP / 256, 256>>>(idx_i);
    k_scan<<<1, 1024>>>();
    k_scatter<<<NP / 256, 256>>>(idx_i);

    for (int b = 0; b < NB; b++) {
        k_x<<<NA / TMX, 128>>>(q,
                               int_W1 + b * FDIM * FDIM, int_b1 + b * FDIM,
                               int_W2 + b * FDIM * 384, int_b2 + b * 384,
                               xbuf);
        k_pairs_g<<<NA / 4, 128>>>(xbuf, mu, distances, vectors, cutoffs, rbfs,
                                   filter_W + b * 384, filter_b + b * 384,
                                   idx_j, dqbuf, dmubuf);
        k_mix<<<NA / 8, 128>>>(q, mu, dqbuf, dmubuf,
                               mix_Wv + b * FDIM * 256,
                               mix_W1 + b * 256 * FDIM, mix_b1 + b * FDIM,
                               mix_W2 + b * FDIM * 384, mix_b2 + b * 384);
    }
}

// round 11
// speedup vs baseline: 1.3275x; 1.3275x over previous
#include <cuda_runtime.h>
#include <cuda_bf16.h>

#define NA 8192
#define NP 65536
#define FDIM 128
#define RD 20
#define NB 5
#define TMX 8

// Scratch (allocation-free rule: __device__ globals)
__device__ __align__(16) float g_x[NA * 384];
__device__ __align__(16) float g_dq[NA * FDIM];
__device__ __align__(16) float g_dmu[NA * 384];
__device__ __align__(16) float g_desc[NP * 384];   // per-block filter descriptors

__device__ __forceinline__ float silu(float z) { return z / (1.f + __expf(-z)); }

__device__ __forceinline__ void red4(float* p, float a, float b, float c, float d) {
    asm volatile("red.global.add.v4.f32 [%0], {%1,%2,%3,%4};"
                 :: "l"(p), "f"(a), "f"(b), "f"(c), "f"(d) : "memory");
}

// ---------------------------------------------------------------------------
// k_filter: desc[p, 0:384] = (rbf[p] @ fW + fb) * cut[p]   for one block b.
// CTA = 384 threads (12 warps), 32 pairs per CTA. Warp w: slice s=w%3 owns
// 32 float4 columns, octet o=w/3 owns 8 pairs -> fW LDS.128 amortized 8x.
// ---------------------------------------------------------------------------
__global__ void __launch_bounds__(384) k_filter(
    const float* __restrict__ rbf, const float* __restrict__ cut,
    const float* __restrict__ fW,   // pre-offset by b*384, row stride 1920
    const float* __restrict__ fb,   // pre-offset by b*384
    float* __restrict__ desc)
{
    __shared__ __align__(16) float fw_s[RD * 384];
    __shared__ __align__(16) float fb_s[384];
    __shared__ float rbf_s[32][RD];
    __shared__ float cut_s[32];
    const int tid = threadIdx.x;
    const int p0 = blockIdx.x * 32;

    for (int c = tid; c < RD * 384; c += 384) {
        int r = c / 384, cc = c - r * 384;
        fw_s[c] = fW[r * 1920 + cc];
    }
    fb_s[tid] = fb[tid];
    for (int c = tid; c < 32 * RD; c += 384)
        rbf_s[c / RD][c % RD] = rbf[(p0 + c / RD) * RD + (c % RD)];
    if (tid < 32) cut_s[tid] = cut[p0 + tid];
    __syncthreads();

    const int w = tid >> 5, lane = tid & 31;
    const int s = w % 3;
    const int o = w / 3;
    const float4* fw4 = (const float4*)fw_s;     // [RD][96]
    const float4 bv = ((const float4*)fb_s)[s * 32 + lane];

    float4 acc[8];
#pragma unroll
    for (int pp = 0; pp < 8; pp++) acc[pp] = make_float4(0.f, 0.f, 0.f, 0.f);
#pragma unroll
    for (int r = 0; r < RD; r++) {
        float4 wv = fw4[r * 96 + s * 32 + lane];
#pragma unroll
        for (int pp = 0; pp < 8; pp++) {
            float rb = rbf_s[o * 8 + pp][r];
            acc[pp].x += rb * wv.x; acc[pp].y += rb * wv.y;
            acc[pp].z += rb * wv.z; acc[pp].w += rb * wv.w;
        }
    }
    float4* out = (float4*)desc;
#pragma unroll
    for (int pp = 0; pp < 8; pp++) {
        const int p = p0 + o * 8 + pp;
        const float cu = cut_s[o * 8 + pp];
        float4 v;
        v.x = (acc[pp].x + bv.x) * cu; v.y = (acc[pp].y + bv.y) * cu;
        v.z = (acc[pp].z + bv.z) * cu; v.w = (acc[pp].w + bv.w) * cu;
        out[p * 96 + s * 32 + lane] = v;
    }
}

// ---------------------------------------------------------------------------
// k_x: x = silu(q @ W1 + b1) @ W2 + b2.  8 atoms/CTA, 128 threads, 1 col/thr.
// (R7-proven)
// ---------------------------------------------------------------------------
__global__ void __launch_bounds__(128) k_x(
    const float* __restrict__ q,
    const float* __restrict__ W1, const float* __restrict__ b1,
    const float* __restrict__ W2, const float* __restrict__ b2,
    float* __restrict__ x)
{
    __shared__ __align__(16) float qs[TMX * FDIM];
    __shared__ __align__(16) float hs[TMX * FDIM];
    const int tid = threadIdx.x;
    const int atom0 = blockIdx.x * TMX;
    const int f = tid;

    {
        const float4* src = (const float4*)(q + atom0 * FDIM);
        float4* dst = (float4*)qs;
        for (int c = tid; c < TMX * 32; c += 128) dst[c] = src[c];
    }
    __syncthreads();

    const float4* qs4 = (const float4*)qs;
    {
        float acc[TMX];
#pragma unroll
        for (int a = 0; a < TMX; a++) acc[a] = 0.f;
#pragma unroll 2
        for (int kp = 0; kp < 32; kp++) {
            const float w0 = W1[(4 * kp)     * FDIM + f];
            const float w1 = W1[(4 * kp + 1) * FDIM + f];
            const float w2 = W1[(4 * kp + 2) * FDIM + f];
            const float w3 = W1[(4 * kp + 3) * FDIM + f];
#pragma unroll
            for (int a = 0; a < TMX; a++) {
                const float4 v = qs4[a * 32 + kp];
                acc[a] += v.x * w0 + v.y * w1 + v.z * w2 + v.w * w3;
            }
        }
        const float bb = b1[f];
#pragma unroll
        for (int a = 0; a < TMX; a++) hs[a * FDIM + f] = silu(acc[a] + bb);
    }
    __syncthreads();

    {
        const float4* hs4 = (const float4*)hs;
        float accA[TMX], accB[TMX], accC[TMX];
#pragma unroll
        for (int a = 0; a < TMX; a++) { accA[a] = 0.f; accB[a] = 0.f; accC[a] = 0.f; }
#pragma unroll 2
        for (int kp = 0; kp < 32; kp++) {
            float wa[4], wb[4], wc[4];
#pragma unroll
            for (int t = 0; t < 4; t++) {
                wa[t] = W2[(4 * kp + t) * 384 + f];
                wb[t] = W2[(4 * kp + t) * 384 + FDIM + f];
                wc[t] = W2[(4 * kp + t) * 384 + 2 * FDIM + f];
            }
#pragma unroll
            for (int a = 0; a < TMX; a++) {
                const float4 v = hs4[a * 32 + kp];
                accA[a] += v.x * wa[0] + v.y * wa[1] + v.z * wa[2] + v.w * wa[3];
                accB[a] += v.x * wb[0] + v.y * wb[1] + v.z * wb[2] + v.w * wb[3];
                accC[a] += v.x * wc[0] + v.y * wc[1] + v.z * wc[2] + v.w * wc[3];
            }
        }
        const float bA = b2[f], bB = b2[FDIM + f], bC = b2[2 * FDIM + f];
#pragma unroll
        for (int a = 0; a < TMX; a++) {
            x[(atom0 + a) * 384 + f]            = accA[a] + bA;
            x[(atom0 + a) * 384 + FDIM + f]     = accB[a] + bB;
            x[(atom0 + a) * 384 + 2 * FDIM + f] = accC[a] + bC;
        }
    }
}

// ---------------------------------------------------------------------------
// k_pairs: slim gather + RED scatter. One warp per pair iteration, lane = 4
// features. desc read from L2 (materialized by k_filter). No dependent load
// chains, no carried accumulators -> deep MLP.
// ---------------------------------------------------------------------------
__global__ void __launch_bounds__(128) k_pairs(
    const float* __restrict__ x, const float* __restrict__ mu,
    const float* __restrict__ desc,
    const float* __restrict__ dist, const float* __restrict__ vec,
    const int* __restrict__ idx_i, const int* __restrict__ idx_j,
    float* __restrict__ dq, float* __restrict__ dmu)
{
    const int lane = threadIdx.x & 31;
    const int gw = blockIdx.x * 4 + (threadIdx.x >> 5);
    const int nw = gridDim.x * 4;
    const float4* D4 = (const float4*)desc;    // [NP][96]
    const float4* X4 = (const float4*)x;       // [NA][96]
    const float4* M4 = (const float4*)mu;      // [NA*3][32]

    for (int p = gw; p < NP; p += nw) {
        const int i = idx_i[p];
        const int j = idx_j[p];
        const float dinv = 1.f / dist[p];
        const float d0 = vec[3 * p] * dinv;
        const float d1 = vec[3 * p + 1] * dinv;
        const float d2 = vec[3 * p + 2] * dinv;

        const float4 wq = D4[p * 96 + lane];
        const float4 wr = D4[p * 96 + 32 + lane];
        const float4 wm = D4[p * 96 + 64 + lane];
        const float4 xq = X4[j * 96 + lane];
        const float4 xr = X4[j * 96 + 32 + lane];
        const float4 xm = X4[j * 96 + 64 + lane];

        red4(dq + i * FDIM + lane * 4,
             xq.x * wq.x, xq.y * wq.y, xq.z * wq.z, xq.w * wq.w);

        const float ax = xr.x * wr.x, ay = xr.y * wr.y, az = xr.z * wr.z, aw = xr.w * wr.w;
        const float cx = xm.x * wm.x, cy = xm.y * wm.y, cz = xm.z * wm.z, cw = xm.w * wm.w;
#pragma unroll
        for (int d = 0; d < 3; d++) {
            const float dd = (d == 0) ? d0 : ((d == 1) ? d1 : d2);
            const float4 mj = M4[(j * 3 + d) * 32 + lane];
            red4(dmu + (i * 3 + d) * FDIM + lane * 4,
                 ax * dd + cx * mj.x,
                 ay * dd + cy * mj.y,
                 az * dd + cz * mj.z,
                 aw * dd + cw * mj.w);
        }
    }
}

// ---------------------------------------------------------------------------
// k_mix (R7-proven): fold deltas; mu@Wv with running norm^2 and V.W dot in
// registers; mixing MLP; gated update. 8 atoms/CTA, 128 threads, 1 col/thr.
// ---------------------------------------------------------------------------
__global__ void __launch_bounds__(128) k_mix(
    float* __restrict__ q, float* __restrict__ mu,
    const float* __restrict__ dq, const float* __restrict__ dmu,
    const float* __restrict__ Wv,                                  // [128][256]
    const float* __restrict__ mW1, const float* __restrict__ mb1,  // [256][128]
    const float* __restrict__ mW2, const float* __restrict__ mb2)  // [128][384]
{
    __shared__ __align__(16) float qs[8 * FDIM];
    __shared__ __align__(16) float mus[8 * 384];
    __shared__ __align__(16) float mws[8 * 384];
    __shared__ __align__(16) float ns[8 * FDIM];
    __shared__ __align__(16) float hs[8 * FDIM];

    const int tid = threadIdx.x;
    const int atom0 = blockIdx.x * 8;
    const int f = tid;

    {
        const float4* sq = (const float4*)(q + atom0 * FDIM);
        const float4* sdq = (const float4*)(dq + atom0 * FDIM);
        float4* dst = (float4*)qs;
        for (int c = tid; c < 8 * 32; c += 128) {
            float4 a = sq[c], b = sdq[c];
            dst[c] = make_float4(a.x + b.x, a.y + b.y, a.z + b.z, a.w + b.w);
        }
        const float4* sm = (const float4*)(mu + atom0 * 384);
        const float4* sdm = (const float4*)(dmu + atom0 * 384);
        float4* dstm = (float4*)mus;
        for (int c = tid; c < 8 * 96; c += 128) {
            float4 a = sm[c], b = sdm[c];
            dstm[c] = make_float4(a.x + b.x, a.y + b.y, a.z + b.z, a.w + b.w);
        }
    }
    __syncthreads();

    const float4* mus4 = (const float4*)mus;
    float nsq[8], dot[8];
#pragma unroll
    for (int a = 0; a < 8; a++) { nsq[a] = 0.f; dot[a] = 0.f; }

#pragma unroll 1
    for (int d = 0; d < 3; d++) {
        float accV[8], accW[8];
#pragma unroll
        for (int a = 0; a < 8; a++) { accV[a] = 0.f; accW[a] = 0.f; }
#pragma unroll 2
        for (int kp = 0; kp < 32; kp++) {
            float wv[4], ww[4];
#pragma unroll
            for (int t = 0; t < 4; t++) {
                wv[t] = Wv[(4 * kp + t) * 256 + f];
                ww[t] = Wv[(4 * kp + t) * 256 + FDIM + f];
            }
#pragma unroll
            for (int a = 0; a < 8; a++) {
                const float4 m = mus4[a * 96 + d * 32 + kp];
                accV[a] += m.x * wv[0] + m.y * wv[1] + m.z * wv[2] + m.w * wv[3];
                accW[a] += m.x * ww[0] + m.y * ww[1] + m.z * ww[2] + m.w * ww[3];
            }
        }
#pragma unroll
        for (int a = 0; a < 8; a++) {
            mws[a * 384 + d * FDIM + f] = accW[a];
            nsq[a] += accV[a] * accV[a];
            dot[a] += accV[a] * accW[a];
        }
    }
#pragma unroll
    for (int a = 0; a < 8; a++) ns[a * FDIM + f] = sqrtf(nsq[a] + 1e-8f);
    __syncthreads();

    {
        const float4* qs4 = (const float4*)qs;
        const float4* ns4 = (const float4*)ns;
        float acc[8];
#pragma unroll
        for (int a = 0; a < 8; a++) acc[a] = 0.f;
#pragma unroll 2
        for (int kp = 0; kp < 32; kp++) {
            float w[4];
#pragma unroll
            for (int t = 0; t < 4; t++) w[t] = mW1[(4 * kp + t) * FDIM + f];
#pragma unroll
            for (int a = 0; a < 8; a++) {
                const float4 v = qs4[a * 32 + kp];
                acc[a] += v.x * w[0] + v.y * w[1] + v.z * w[2] + v.w * w[3];
            }
        }
#pragma unroll 2
        for (int kp = 0; kp < 32; kp++) {
            float w[4];
#pragma unroll
            for (int t = 0; t < 4; t++) w[t] = mW1[(FDIM + 4 * kp + t) * FDIM + f];
#pragma unroll
            for (int a = 0; a < 8; a++) {
                const float4 v = ns4[a * 32 + kp];
                acc[a] += v.x * w[0] + v.y * w[1] + v.z * w[2] + v.w * w[3];
            }
        }
        const float bb = mb1[f];
#pragma unroll
        for (int a = 0; a < 8; a++) hs[a * FDIM + f] = silu(acc[a] + bb);
    }
    __syncthreads();

    {
        const float4* hs4 = (const float4*)hs;
        float accA[8], accB[8], accC[8];
#pragma unroll
        for (int a = 0; a < 8; a++) { accA[a] = 0.f; accB[a] = 0.f; accC[a] = 0.f; }
#pragma unroll 2
        for (int kp = 0; kp < 32; kp++) {
            float wa[4], wb[4], wc[4];
#pragma unroll
            for (int t = 0; t < 4; t++) {
                wa[t] = mW2[(4 * kp + t) * 384 + f];
                wb[t] = mW2[(4 * kp + t) * 384 + FDIM + f];
                wc[t] = mW2[(4 * kp + t) * 384 + 2 * FDIM + f];
            }
#pragma unroll
            for (int a = 0; a < 8; a++) {
                const float4 v = hs4[a * 32 + kp];
                accA[a] += v.x * wa[0] + v.y * wa[1] + v.z * wa[2] + v.w * wa[3];
                accB[a] += v.x * wb[0] + v.y * wb[1] + v.z * wb[2] + v.w * wb[3];
                accC[a] += v.x * wc[0] + v.y * wc[1] + v.z * wc[2] + v.w * wc[3];
            }
        }
        const float bA = mb2[f], bB = mb2[FDIM + f], bC = mb2[2 * FDIM + f];
#pragma unroll
        for (int a = 0; a < 8; a++) {
            const float yA = accA[a] + bA;
            const float yB = accB[a] + bB;
            const float yC = accC[a] + bC;
            q[(atom0 + a) * FDIM + f] = qs[a * FDIM + f] + yA + yC * dot[a];
#pragma unroll
            for (int d = 0; d < 3; d++)
                mu[(atom0 + a) * 384 + d * FDIM + f] =
                    mus[a * 384 + d * FDIM + f] + yB * mws[a * 384 + d * FDIM + f];
        }
    }
}

// ---------------------------------------------------------------------------
extern "C" void kernel_launch(void* const* d_in, const int* in_sizes, int n_in,
                              void* d_out, int out_size)
{
    const float* features = (const float*)d_in[0];
    const float* distances = (const float*)d_in[1];
    const float* vectors = (const float*)d_in[2];
    const float* cutoffs = (const float*)d_in[3];
    const float* rbfs = (const float*)d_in[4];
    const float* filter_W = (const float*)d_in[5];
    const float* filter_b = (const float*)d_in[6];
    const float* int_W1 = (const float*)d_in[7];
    const float* int_b1 = (const float*)d_in[8];
    const float* int_W2 = (const float*)d_in[9];
    const float* int_b2 = (const float*)d_in[10];
    const float* mix_Wv = (const float*)d_in[11];
    const float* mix_W1 = (const float*)d_in[12];
    const float* mix_b1 = (const float*)d_in[13];
    const float* mix_W2 = (const float*)d_in[14];
    const float* mix_b2 = (const float*)d_in[15];
    const int* idx_i = (const int*)d_in[16];
    const int* idx_j = (const int*)d_in[17];

    float* q = (float*)d_out;            // [NA,128]
    float* mu = q + NA * FDIM;           // [NA,3,128]

    float *xbuf, *dqbuf, *dmubuf, *descbuf;
    cudaGetSymbolAddress((void**)&xbuf, g_x);
    cudaGetSymbolAddress((void**)&dqbuf, g_dq);
    cudaGetSymbolAddress((void**)&dmubuf, g_dmu);
    cudaGetSymbolAddress((void**)&descbuf, g_desc);

    cudaMemcpyAsync(q, features, NA * FDIM * sizeof(float), cudaMemcpyDeviceToDevice);
    cudaMemsetAsync(mu, 0, NA * 384 * sizeof(float));

    for (int b = 0; b < NB; b++) {
        k_filter<<<NP / 32, 384>>>(rbfs, cutoffs,
                                   filter_W + b * 384, filter_b + b * 384,
                                   descbuf);
        k_x<<<NA / TMX, 128>>>(q,
                               int_W1 + b * FDIM * FDIM, int_b1 + b * FDIM,
                               int_W2 + b * FDIM * 384, int_b2 + b * 384,
                               xbuf);
        cudaMemsetAsync(dqbuf, 0, NA * FDIM * sizeof(float));
        cudaMemsetAsync(dmubuf, 0, NA * 384 * sizeof(float));
        k_pairs<<<2048, 128>>>(xbuf, mu, descbuf, distances, vectors,
                               idx_i, idx_j, dqbuf, dmubuf);
        k_mix<<<NA / 8, 128>>>(q, mu, dqbuf, dmubuf,
                               mix_Wv + b * FDIM * 256,
                               mix_W1 + b * 256 * FDIM, mix_b1 + b * FDIM,
                               mix_W2 + b * FDIM * 384, mix_b2 + b * 384);
    }
}

// round 12
// speedup vs baseline: 1.5130x; 1.1397x over previous
#include <cuda_runtime.h>
#include <cuda_bf16.h>

#define NA 8192
#define NP 65536
#define FDIM 128
#define RD 20
#define NB 5
#define TMX 8

// Scratch (allocation-free rule: __device__ globals)
__device__ __align__(16) float g_x[NA * 384];
__device__ __align__(16) float g_dq[NA * FDIM];
__device__ __align__(16) float g_dmu[NA * 384];

__device__ __forceinline__ float silu(float z) { return z / (1.f + __expf(-z)); }

__device__ __forceinline__ void red4(float* p, float a, float b, float c, float d) {
    asm volatile("red.global.add.v4.f32 [%0], {%1,%2,%3,%4};"
                 :: "l"(p), "f"(a), "f"(b), "f"(c), "f"(d) : "memory");
}

// ---------------------------------------------------------------------------
// k_x (R7-proven): x = silu(q @ W1 + b1) @ W2 + b2. 8 atoms/CTA, 128 thr.
// ---------------------------------------------------------------------------
__global__ void __launch_bounds__(128) k_x(
    const float* __restrict__ q,
    const float* __restrict__ W1, const float* __restrict__ b1,
    const float* __restrict__ W2, const float* __restrict__ b2,
    float* __restrict__ x)
{
    __shared__ __align__(16) float qs[TMX * FDIM];
    __shared__ __align__(16) float hs[TMX * FDIM];
    const int tid = threadIdx.x;
    const int atom0 = blockIdx.x * TMX;
    const int f = tid;

    {
        const float4* src = (const float4*)(q + atom0 * FDIM);
        float4* dst = (float4*)qs;
        for (int c = tid; c < TMX * 32; c += 128) dst[c] = src[c];
    }
    __syncthreads();

    const float4* qs4 = (const float4*)qs;
    {
        float acc[TMX];
#pragma unroll
        for (int a = 0; a < TMX; a++) acc[a] = 0.f;
#pragma unroll 2
        for (int kp = 0; kp < 32; kp++) {
            const float w0 = W1[(4 * kp)     * FDIM + f];
            const float w1 = W1[(4 * kp + 1) * FDIM + f];
            const float w2 = W1[(4 * kp + 2) * FDIM + f];
            const float w3 = W1[(4 * kp + 3) * FDIM + f];
#pragma unroll
            for (int a = 0; a < TMX; a++) {
                const float4 v = qs4[a * 32 + kp];
                acc[a] += v.x * w0 + v.y * w1 + v.z * w2 + v.w * w3;
            }
        }
        const float bb = b1[f];
#pragma unroll
        for (int a = 0; a < TMX; a++) hs[a * FDIM + f] = silu(acc[a] + bb);
    }
    __syncthreads();

    {
        const float4* hs4 = (const float4*)hs;
        float accA[TMX], accB[TMX], accC[TMX];
#pragma unroll
        for (int a = 0; a < TMX; a++) { accA[a] = 0.f; accB[a] = 0.f; accC[a] = 0.f; }
#pragma unroll 2
        for (int kp = 0; kp < 32; kp++) {
            float wa[4], wb[4], wc[4];
#pragma unroll
            for (int t = 0; t < 4; t++) {
                wa[t] = W2[(4 * kp + t) * 384 + f];
                wb[t] = W2[(4 * kp + t) * 384 + FDIM + f];
                wc[t] = W2[(4 * kp + t) * 384 + 2 * FDIM + f];
            }
#pragma unroll
            for (int a = 0; a < TMX; a++) {
                const float4 v = hs4[a * 32 + kp];
                accA[a] += v.x * wa[0] + v.y * wa[1] + v.z * wa[2] + v.w * wa[3];
                accB[a] += v.x * wb[0] + v.y * wb[1] + v.z * wb[2] + v.w * wb[3];
                accC[a] += v.x * wc[0] + v.y * wc[1] + v.z * wc[2] + v.w * wc[3];
            }
        }
        const float bA = b2[f], bB = b2[FDIM + f], bC = b2[2 * FDIM + f];
#pragma unroll
        for (int a = 0; a < TMX; a++) {
            x[(atom0 + a) * 384 + f]            = accA[a] + bA;
            x[(atom0 + a) * 384 + FDIM + f]     = accB[a] + bB;
            x[(atom0 + a) * 384 + 2 * FDIM + f] = accC[a] + bC;
        }
    }
}

// ---------------------------------------------------------------------------
// k_pairs: fused filter + gather + RED scatter, 4 PAIRS PER WARP so each
// filter-weight LDS.128 serves 4 pairs (crossbar traffic /4).
// ---------------------------------------------------------------------------
__global__ void __launch_bounds__(128) k_pairs(
    const float* __restrict__ x, const float* __restrict__ mu,
    const float* __restrict__ dist, const float* __restrict__ vec,
    const float* __restrict__ cut, const float* __restrict__ rbf,
    const float* __restrict__ fW,   // pre-offset by b*384, row stride 1920
    const float* __restrict__ fb,   // pre-offset by b*384
    const int* __restrict__ idx_i, const int* __restrict__ idx_j,
    float* __restrict__ dq, float* __restrict__ dmu)
{
    __shared__ __align__(16) float fw_s[RD * 384];
    __shared__ __align__(16) float fb_s[384];
    const int tid = threadIdx.x;
    for (int c = tid; c < RD * 384; c += 128) {
        int r = c / 384, cc = c - r * 384;
        fw_s[c] = fW[r * 1920 + cc];
    }
    for (int c = tid; c < 384; c += 128) fb_s[c] = fb[c];
    __syncthreads();

    const int lane = tid & 31;
    const int gw = blockIdx.x * 4 + (tid >> 5);
    const int nw = gridDim.x * 4;
    const float4* fw4 = (const float4*)fw_s;   // [RD][96]
    const float4* fb4 = (const float4*)fb_s;   // [96]
    const float4* X4 = (const float4*)x;       // [NA][96]
    const float4* M4 = (const float4*)mu;      // [NA*3][32]

    const float4 fbq = fb4[lane];
    const float4 fbr = fb4[32 + lane];
    const float4 fbm = fb4[64 + lane];

    for (int g = gw; g < NP / 4; g += nw) {
        const int pbase = g * 4;

        int ii[4], jj[4];
        float cu[4], e0[4], e1[4], e2[4];
#pragma unroll
        for (int pp = 0; pp < 4; pp++) {
            const int p = pbase + pp;
            ii[pp] = idx_i[p];
            jj[pp] = idx_j[p];
            const float dinv = 1.f / dist[p];
            cu[pp] = cut[p];
            e0[pp] = vec[3 * p] * dinv;
            e1[pp] = vec[3 * p + 1] * dinv;
            e2[pp] = vec[3 * p + 2] * dinv;
        }

        float4 wq[4], wr[4], wm[4];
#pragma unroll
        for (int pp = 0; pp < 4; pp++) {
            wq[pp] = make_float4(0.f, 0.f, 0.f, 0.f);
            wr[pp] = wq[pp]; wm[pp] = wq[pp];
        }
#pragma unroll 4
        for (int r = 0; r < RD; r++) {
            const float4 t0 = fw4[r * 96 + lane];
            const float4 t1 = fw4[r * 96 + 32 + lane];
            const float4 t2 = fw4[r * 96 + 64 + lane];
#pragma unroll
            for (int pp = 0; pp < 4; pp++) {
                const float rb = rbf[(pbase + pp) * RD + r];
                wq[pp].x += rb * t0.x; wq[pp].y += rb * t0.y;
                wq[pp].z += rb * t0.z; wq[pp].w += rb * t0.w;
                wr[pp].x += rb * t1.x; wr[pp].y += rb * t1.y;
                wr[pp].z += rb * t1.z; wr[pp].w += rb * t1.w;
                wm[pp].x += rb * t2.x; wm[pp].y += rb * t2.y;
                wm[pp].z += rb * t2.z; wm[pp].w += rb * t2.w;
            }
        }

#pragma unroll
        for (int pp = 0; pp < 4; pp++) {
            const int i = ii[pp];
            const int j = jj[pp];
            const float c = cu[pp];
            const float4 WQ = make_float4((wq[pp].x + fbq.x) * c, (wq[pp].y + fbq.y) * c,
                                          (wq[pp].z + fbq.z) * c, (wq[pp].w + fbq.w) * c);
            const float4 WR = make_float4((wr[pp].x + fbr.x) * c, (wr[pp].y + fbr.y) * c,
                                          (wr[pp].z + fbr.z) * c, (wr[pp].w + fbr.w) * c);
            const float4 WM = make_float4((wm[pp].x + fbm.x) * c, (wm[pp].y + fbm.y) * c,
                                          (wm[pp].z + fbm.z) * c, (wm[pp].w + fbm.w) * c);

            const float4 xq = X4[j * 96 + lane];
            const float4 xr = X4[j * 96 + 32 + lane];
            const float4 xm = X4[j * 96 + 64 + lane];

            red4(dq + i * FDIM + lane * 4,
                 xq.x * WQ.x, xq.y * WQ.y, xq.z * WQ.z, xq.w * WQ.w);

            const float ax = xr.x * WR.x, ay = xr.y * WR.y, az = xr.z * WR.z, aw = xr.w * WR.w;
            const float cx = xm.x * WM.x, cy = xm.y * WM.y, cz = xm.z * WM.z, cw = xm.w * WM.w;

            const float d0 = e0[pp], d1 = e1[pp], d2 = e2[pp];
            const float4 mj0 = M4[(j * 3 + 0) * 32 + lane];
            red4(dmu + (i * 3 + 0) * FDIM + lane * 4,
                 ax * d0 + cx * mj0.x, ay * d0 + cy * mj0.y,
                 az * d0 + cz * mj0.z, aw * d0 + cw * mj0.w);
            const float4 mj1 = M4[(j * 3 + 1) * 32 + lane];
            red4(dmu + (i * 3 + 1) * FDIM + lane * 4,
                 ax * d1 + cx * mj1.x, ay * d1 + cy * mj1.y,
                 az * d1 + cz * mj1.z, aw * d1 + cw * mj1.w);
            const float4 mj2 = M4[(j * 3 + 2) * 32 + lane];
            red4(dmu + (i * 3 + 2) * FDIM + lane * 4,
                 ax * d2 + cx * mj2.x, ay * d2 + cy * mj2.y,
                 az * d2 + cz * mj2.z, aw * d2 + cw * mj2.w);
        }
    }
}

// ---------------------------------------------------------------------------
// k_mix (R7-proven): fold deltas; mu@Wv with running norm^2 and V.W dot in
// registers; mixing MLP; gated update. 8 atoms/CTA, 128 threads, 1 col/thr.
// ---------------------------------------------------------------------------
__global__ void __launch_bounds__(128) k_mix(
    float* __restrict__ q, float* __restrict__ mu,
    const float* __restrict__ dq, const float* __restrict__ dmu,
    const float* __restrict__ Wv,                                  // [128][256]
    const float* __restrict__ mW1, const float* __restrict__ mb1,  // [256][128]
    const float* __restrict__ mW2, const float* __restrict__ mb2)  // [128][384]
{
    __shared__ __align__(16) float qs[8 * FDIM];
    __shared__ __align__(16) float mus[8 * 384];
    __shared__ __align__(16) float mws[8 * 384];
    __shared__ __align__(16) float ns[8 * FDIM];
    __shared__ __align__(16) float hs[8 * FDIM];

    const int tid = threadIdx.x;
    const int atom0 = blockIdx.x * 8;
    const int f = tid;

    {
        const float4* sq = (const float4*)(q + atom0 * FDIM);
        const float4* sdq = (const float4*)(dq + atom0 * FDIM);
        float4* dst = (float4*)qs;
        for (int c = tid; c < 8 * 32; c += 128) {
            float4 a = sq[c], b = sdq[c];
            dst[c] = make_float4(a.x + b.x, a.y + b.y, a.z + b.z, a.w + b.w);
        }
        const float4* sm = (const float4*)(mu + atom0 * 384);
        const float4* sdm = (const float4*)(dmu + atom0 * 384);
        float4* dstm = (float4*)mus;
        for (int c = tid; c < 8 * 96; c += 128) {
            float4 a = sm[c], b = sdm[c];
            dstm[c] = make_float4(a.x + b.x, a.y + b.y, a.z + b.z, a.w + b.w);
        }
    }
    __syncthreads();

    const float4* mus4 = (const float4*)mus;
    float nsq[8], dot[8];
#pragma unroll
    for (int a = 0; a < 8; a++) { nsq[a] = 0.f; dot[a] = 0.f; }

#pragma unroll 1
    for (int d = 0; d < 3; d++) {
        float accV[8], accW[8];
#pragma unroll
        for (int a = 0; a < 8; a++) { accV[a] = 0.f; accW[a] = 0.f; }
#pragma unroll 2
        for (int kp = 0; kp < 32; kp++) {
            float wv[4], ww[4];
#pragma unroll
            for (int t = 0; t < 4; t++) {
                wv[t] = Wv[(4 * kp + t) * 256 + f];
                ww[t] = Wv[(4 * kp + t) * 256 + FDIM + f];
            }
#pragma unroll
            for (int a = 0; a < 8; a++) {
                const float4 m = mus4[a * 96 + d * 32 + kp];
                accV[a] += m.x * wv[0] + m.y * wv[1] + m.z * wv[2] + m.w * wv[3];
                accW[a] += m.x * ww[0] + m.y * ww[1] + m.z * ww[2] + m.w * ww[3];
            }
        }
#pragma unroll
        for (int a = 0; a < 8; a++) {
            mws[a * 384 + d * FDIM + f] = accW[a];
            nsq[a] += accV[a] * accV[a];
            dot[a] += accV[a] * accW[a];
        }
    }
#pragma unroll
    for (int a = 0; a < 8; a++) ns[a * FDIM + f] = sqrtf(nsq[a] + 1e-8f);
    __syncthreads();

    {
        const float4* qs4 = (const float4*)qs;
        const float4* ns4 = (const float4*)ns;
        float acc[8];
#pragma unroll
        for (int a = 0; a < 8; a++) acc[a] = 0.f;
#pragma unroll 2
        for (int kp = 0; kp < 32; kp++) {
            float w[4];
#pragma unroll
            for (int t = 0; t < 4; t++) w[t] = mW1[(4 * kp + t) * FDIM + f];
#pragma unroll
            for (int a = 0; a < 8; a++) {
                const float4 v = qs4[a * 32 + kp];
                acc[a] += v.x * w[0] + v.y * w[1] + v.z * w[2] + v.w * w[3];
            }
        }
#pragma unroll 2
        for (int kp = 0; kp < 32; kp++) {
            float w[4];
#pragma unroll
            for (int t = 0; t < 4; t++) w[t] = mW1[(FDIM + 4 * kp + t) * FDIM + f];
#pragma unroll
            for (int a = 0; a < 8; a++) {
                const float4 v = ns4[a * 32 + kp];
                acc[a] += v.x * w[0] + v.y * w[1] + v.z * w[2] + v.w * w[3];
            }
        }
        const float bb = mb1[f];
#pragma unroll
        for (int a = 0; a < 8; a++) hs[a * FDIM + f] = silu(acc[a] + bb);
    }
    __syncthreads();

    {
        const float4* hs4 = (const float4*)hs;
        float accA[8], accB[8], accC[8];
#pragma unroll
        for (int a = 0; a < 8; a++) { accA[a] = 0.f; accB[a] = 0.f; accC[a] = 0.f; }
#pragma unroll 2
        for (int kp = 0; kp < 32; kp++) {
            float wa[4], wb[4], wc[4];
#pragma unroll
            for (int t = 0; t < 4; t++) {
                wa[t] = mW2[(4 * kp + t) * 384 + f];
                wb[t] = mW2[(4 * kp + t) * 384 + FDIM + f];
                wc[t] = mW2[(4 * kp + t) * 384 + 2 * FDIM + f];
            }
#pragma unroll
            for (int a = 0; a < 8; a++) {
                const float4 v = hs4[a * 32 + kp];
                accA[a] += v.x * wa[0] + v.y * wa[1] + v.z * wa[2] + v.w * wa[3];
                accB[a] += v.x * wb[0] + v.y * wb[1] + v.z * wb[2] + v.w * wb[3];
                accC[a] += v.x * wc[0] + v.y * wc[1] + v.z * wc[2] + v.w * wc[3];
            }
        }
        const float bA = mb2[f], bB = mb2[FDIM + f], bC = mb2[2 * FDIM + f];
#pragma unroll
        for (int a = 0; a < 8; a++) {
            const float yA = accA[a] + bA;
            const float yB = accB[a] + bB;
            const float yC = accC[a] + bC;
            q[(atom0 + a) * FDIM + f] = qs[a * FDIM + f] + yA + yC * dot[a];
#pragma unroll
            for (int d = 0; d < 3; d++)
                mu[(atom0 + a) * 384 + d * FDIM + f] =
                    mus[a * 384 + d * FDIM + f] + yB * mws[a * 384 + d * FDIM + f];
        }
    }
}

// ---------------------------------------------------------------------------
extern "C" void kernel_launch(void* const* d_in, const int* in_sizes, int n_in,
                              void* d_out, int out_size)
{
    const float* features = (const float*)d_in[0];
    const float* distances = (const float*)d_in[1];
    const float* vectors = (const float*)d_in[2];
    const float* cutoffs = (const float*)d_in[3];
    const float* rbfs = (const float*)d_in[4];
    const float* filter_W = (const float*)d_in[5];
    const float* filter_b = (const float*)d_in[6];
    const float* int_W1 = (const float*)d_in[7];
    const float* int_b1 = (const float*)d_in[8];
    const float* int_W2 = (const float*)d_in[9];
    const float* int_b2 = (const float*)d_in[10];
    const float* mix_Wv = (const float*)d_in[11];
    const float* mix_W1 = (const float*)d_in[12];
    const float* mix_b1 = (const float*)d_in[13];
    const float* mix_W2 = (const float*)d_in[14];
    const float* mix_b2 = (const float*)d_in[15];
    const int* idx_i = (const int*)d_in[16];
    const int* idx_j = (const int*)d_in[17];

    float* q = (float*)d_out;            // [NA,128]
    float* mu = q + NA * FDIM;           // [NA,3,128]

    float *xbuf, *dqbuf, *dmubuf;
    cudaGetSymbolAddress((void**)&xbuf, g_x);
    cudaGetSymbolAddress((void**)&dqbuf, g_dq);
    cudaGetSymbolAddress((void**)&dmubuf, g_dmu);

    cudaMemcpyAsync(q, features, NA * FDIM * sizeof(float), cudaMemcpyDeviceToDevice);
    cudaMemsetAsync(mu, 0, NA * 384 * sizeof(float));

    for (int b = 0; b < NB; b++) {
        k_x<<<NA / TMX, 128>>>(q,
                               int_W1 + b * FDIM * FDIM, int_b1 + b * FDIM,
                               int_W2 + b * FDIM * 384, int_b2 + b * 384,
                               xbuf);
        cudaMemsetAsync(dqbuf, 0, NA * FDIM * sizeof(float));
        cudaMemsetAsync(dmubuf, 0, NA * 384 * sizeof(float));
        k_pairs<<<2048, 128>>>(xbuf, mu, distances, vectors, cutoffs, rbfs,
                               filter_W + b * 384, filter_b + b * 384,
                               idx_i, idx_j, dqbuf, dmubuf);
        k_mix<<<NA / 8, 128>>>(q, mu, dqbuf, dmubuf,
                               mix_Wv + b * FDIM * 256,
                               mix_W1 + b * 256 * FDIM, mix_b1 + b * FDIM,
                               mix_W2 + b * FDIM * 384, mix_b2 + b * 384);
    }
}